// round 8
// baseline (speedup 1.0000x reference)
#include <cuda_runtime.h>
#include <math.h>
#include <stdint.h>

// T1DPatient dx/dt. Persistent kernel, 3-buffer / lookahead-2 TMA pipeline.
// At iter `it` (buffer k=it%3): wait load(k); compute; bulk-store k (commit);
// wait_group.read 1  (drains only the OLDER store group, never the one just
// committed);  issue load(it+2) into a buffer whose store is already drained.
// 3 CTAs/SM x 24KB buffers: ~6 read bursts in flight/SM, stores overlapped.

#define TPB  128
#define TILE 128
#define NBUF 3
#define OFF_X  0            // 13*TILE floats
#define OFF_P  (13 * TILE)  // 30*TILE
#define OFF_S  (43 * TILE)  // 4*TILE (CHO, ins, Qsto, food)
#define BUF_F  (47 * TILE)
#define SMEM_BYTES (NBUF * BUF_F * 4 + 32)

__device__ __forceinline__ uint32_t smem_u32(const void* p) {
    return (uint32_t)__cvta_generic_to_shared(p);
}

__device__ __forceinline__ void bulk_ld(uint32_t dst, const void* src,
                                        uint32_t bytes, uint32_t mbar) {
    asm volatile("cp.async.bulk.shared::cta.global.mbarrier::complete_tx::bytes "
                 "[%0], [%1], %2, [%3];"
                 :: "r"(dst), "l"(src), "r"(bytes), "r"(mbar) : "memory");
}

__global__ void __launch_bounds__(TPB) t1d_dxdt_kernel(
    const float* __restrict__ gx,     // (B,13)
    const float* __restrict__ gp,     // (B,30)
    const float* __restrict__ gCHO,   // (B,)
    const float* __restrict__ gIns,   // (B,)
    const float* __restrict__ gQsto,  // (B,)
    const float* __restrict__ gFood,  // (B,)
    float* __restrict__ gout,         // (B,13)
    int B, int ntiles)
{
    extern __shared__ __align__(16) float smem[];
    uint64_t* mbar = (uint64_t*)(smem + NBUF * BUF_F);

    const int tid = threadIdx.x;
    uint32_t mba[NBUF];
#pragma unroll
    for (int i = 0; i < NBUF; i++) mba[i] = smem_u32(&mbar[i]);

    if (tid == 0) {
#pragma unroll
        for (int i = 0; i < NBUF; i++)
            asm volatile("mbarrier.init.shared.b64 [%0], %1;"
                         :: "r"(mba[i]), "r"(1u));
    }
    __syncthreads();

    auto issue_load = [&](int it) {
        const int t = blockIdx.x + it * gridDim.x;
        if (t >= ntiles) return;
        const int k = it % NBUF;
        float* s = smem + k * BUF_F;
        const int rb = t * TILE;
        const int nr = min(TILE, B - rb);
        if ((nr & 3) == 0) {
            const uint32_t bx = (uint32_t)nr * 13u * 4u;
            const uint32_t bp = (uint32_t)nr * 30u * 4u;
            const uint32_t bs = (uint32_t)nr * 4u;
            asm volatile("mbarrier.arrive.expect_tx.shared.b64 _, [%0], %1;"
                         :: "r"(mba[k]), "r"(bx + bp + 4u * bs) : "memory");
            bulk_ld(smem_u32(s + OFF_X), gx + (size_t)rb * 13, bx, mba[k]);
            bulk_ld(smem_u32(s + OFF_P), gp + (size_t)rb * 30, bp, mba[k]);
            bulk_ld(smem_u32(s + OFF_S + 0 * TILE), gCHO  + rb, bs, mba[k]);
            bulk_ld(smem_u32(s + OFF_S + 1 * TILE), gIns  + rb, bs, mba[k]);
            bulk_ld(smem_u32(s + OFF_S + 2 * TILE), gQsto + rb, bs, mba[k]);
            bulk_ld(smem_u32(s + OFF_S + 3 * TILE), gFood + rb, bs, mba[k]);
        } else {
            asm volatile("mbarrier.arrive.shared.b64 _, [%0];"
                         :: "r"(mba[k]) : "memory");
        }
    };

    if (tid == 0) { issue_load(0); issue_load(1); }

    for (int it = 0;; it++) {
        const int t = blockIdx.x + it * gridDim.x;
        if (t >= ntiles) break;
        const int k = it % NBUF;
        float* s = smem + k * BUF_F;
        const uint32_t ph = (uint32_t)((it / NBUF) & 1);
        const int rb = t * TILE;
        const int nr = min(TILE, B - rb);
        const bool bulk_ok = ((nr & 3) == 0);
        const bool active  = (tid < nr);

        uint32_t done;
        do {
            asm volatile("{\n\t.reg .pred p;\n\t"
                         "mbarrier.try_wait.parity.shared.b64 p, [%1], %2;\n\t"
                         "selp.b32 %0, 1, 0, p;\n\t}"
                         : "=r"(done) : "r"(mba[k]), "r"(ph) : "memory");
        } while (!done);

        if (active) {
            float xv[13];
            float CHO, ins_u, lQ, lF;
            const float* P;
            float pbuf[30];

            if (bulk_ok) {
                const float* X = s + OFF_X + tid * 13;   // stride 13: conflict-free
#pragma unroll
                for (int i = 0; i < 13; i++) xv[i] = X[i];
                P     = s + OFF_P + tid * 30;            // stride 30: 2-way, cheap
                CHO   = s[OFF_S + 0 * TILE + tid];
                ins_u = s[OFF_S + 1 * TILE + tid];
                lQ    = s[OFF_S + 2 * TILE + tid];
                lF    = s[OFF_S + 3 * TILE + tid];
            } else {
                const int row = rb + tid;
#pragma unroll
                for (int i = 0; i < 13; i++) xv[i] = gx[(size_t)row * 13 + i];
#pragma unroll
                for (int i = 0; i < 30; i++) pbuf[i] = gp[(size_t)row * 30 + i];
                P = pbuf;
                CHO = gCHO[row]; ins_u = gIns[row]; lQ = gQsto[row]; lF = gFood[row];
            }

            const float BW      = P[6];
            const float dmg     = CHO * 1000.0f;
            const float insulin = __fdividef(ins_u * 6000.0f, BW);

            const float kmax = P[0], kmin = P[1], b = P[2], d_ = P[3];

            const float qsto = xv[0] + xv[1];
            const float Dbar = lQ + lF;
            const bool  has_food  = (Dbar > 0.0f);
            const float Dbar_safe = has_food ? Dbar : 1.0f;
            const float aa = __fdividef(2.5f, (1.0f - b) * Dbar_safe);
            const float cc = __fdividef(2.5f, d_ * Dbar_safe);
            const float kgut_eating = kmin + (kmax - kmin) * 0.5f *
                (tanhf(aa * (qsto - b * Dbar)) - tanhf(cc * (qsto - d_ * Dbar)) + 2.0f);
            const float kgut = has_food ? kgut_eating : kmax;

            float d[13];
            const float kabs = P[4];
            d[0] = -kmax * xv[0] + dmg;
            d[1] =  kmax * xv[0] - xv[1] * kgut;
            d[2] =  kgut * xv[1] - kabs * xv[2];

            const float Rat  = __fdividef(P[5] * kabs * xv[2], BW);
            const float EGPt = P[7] - P[8] * xv[3] - P[9] * xv[8];
            const float ke1 = P[11], ke2 = P[12];
            const float Et  = (xv[3] > ke2) ? ke1 * (xv[3] - ke2) : 0.0f;
            const float k1 = P[13], k2 = P[14];
            d[3] = (fmaxf(EGPt, 0.0f) + Rat - P[10] - Et - k1 * xv[3] + k2 * xv[4])
                   * (xv[3] >= 0.0f ? 1.0f : 0.0f);

            const float Vmt  = P[15] + P[16] * xv[6];
            const float Uidt = __fdividef(Vmt * xv[4], P[17] + xv[4]);
            d[4] = (-Uidt + k1 * xv[3] - k2 * xv[4]) * (xv[4] >= 0.0f ? 1.0f : 0.0f);

            const float m1 = P[18], m2 = P[19];
            const float ka1 = P[22], ka2 = P[23];
            d[5] = (-(m2 + P[20]) * xv[5] + m1 * xv[9] + ka1 * xv[10] + ka2 * xv[11])
                   * (xv[5] >= 0.0f ? 1.0f : 0.0f);

            const float It  = __fdividef(xv[5], P[25]);
            const float p2u = P[26];
            const float ki  = P[28];
            d[6]  = -p2u * xv[6] + p2u * (It - P[27]);
            d[7]  = -ki * (xv[7] - It);
            d[8]  = -ki * (xv[8] - xv[7]);
            d[9]  = (-(m1 + P[21]) * xv[9] + m2 * xv[5]) * (xv[9]  >= 0.0f ? 1.0f : 0.0f);
            const float kd = P[24];
            d[10] = (insulin - (ka1 + kd) * xv[10])      * (xv[10] >= 0.0f ? 1.0f : 0.0f);
            d[11] = (kd * xv[10] - ka2 * xv[11])         * (xv[11] >= 0.0f ? 1.0f : 0.0f);
            const float ksc = P[29];
            d[12] = (-ksc * xv[12] + ksc * xv[3])        * (xv[12] >= 0.0f ? 1.0f : 0.0f);

            if (bulk_ok) {
                float* O = s + OFF_X + tid * 13;   // overwrite own row only
#pragma unroll
                for (int i = 0; i < 13; i++) O[i] = d[i];
            } else {
                const int row = rb + tid;
#pragma unroll
                for (int i = 0; i < 13; i++) gout[(size_t)row * 13 + i] = d[i];
            }
        }
        __syncthreads();

        if (tid == 0) {
            if (bulk_ok) {
                asm volatile("fence.proxy.async.shared::cta;" ::: "memory");
                asm volatile("cp.async.bulk.global.shared::cta.bulk_group "
                             "[%0], [%1], %2;"
                             :: "l"(gout + (size_t)rb * 13),
                                "r"(smem_u32(s + OFF_X)),
                                "r"((uint32_t)nr * 13u * 4u) : "memory");
            }
            // commit even if empty keeps group accounting uniform
            asm volatile("cp.async.bulk.commit_group;" ::: "memory");
            // drain only the OLDER store group; load(it+2) reuses a buffer
            // whose store is >=2 groups old.
            asm volatile("cp.async.bulk.wait_group.read 1;" ::: "memory");
            issue_load(it + 2);
        }
    }

    if (tid == 0)
        asm volatile("cp.async.bulk.wait_group 0;" ::: "memory");
}

extern "C" void kernel_launch(void* const* d_in, const int* in_sizes, int n_in,
                              void* d_out, int out_size) {
    const float* gx    = (const float*)d_in[0];
    const float* gp    = (const float*)d_in[1];
    const float* gCHO  = (const float*)d_in[2];
    const float* gIns  = (const float*)d_in[3];
    const float* gQ    = (const float*)d_in[4];
    const float* gF    = (const float*)d_in[5];
    float* gout = (float*)d_out;

    const int B = in_sizes[2];
    const int ntiles = (B + TILE - 1) / TILE;

    cudaFuncSetAttribute(t1d_dxdt_kernel,
                         cudaFuncAttributeMaxDynamicSharedMemorySize,
                         SMEM_BYTES);

    int nsm = 0;
    if (cudaDeviceGetAttribute(&nsm, cudaDevAttrMultiProcessorCount, 0)
            != cudaSuccess || nsm <= 0)
        nsm = 148;
    int grid = 3 * nsm;                 // 3 CTAs/SM (72KB smem each)
    if (grid > ntiles) grid = ntiles;

    t1d_dxdt_kernel<<<grid, TPB, SMEM_BYTES>>>(gx, gp, gCHO, gIns, gQ, gF,
                                               gout, B, ntiles);
}

// round 9
// speedup vs baseline: 1.0282x; 1.0282x over previous
#include <cuda_runtime.h>
#include <math.h>
#include <stdint.h>

// T1DPatient dx/dt: B rows; per row x[13], params[30], 4 scalars -> dxdt[13].
// One tile per CTA, bulk-async TMA staging in/out (R7 structure), plus
// L2::evict_first cache hints on all bulk transfers: pure streaming data is
// evicted from L2 promptly, improving DRAM scheduling for the 480MB stream.

#define TPB  128
#define TILE 128
#define OFF_X  0            // 13*TILE floats
#define OFF_P  (13 * TILE)  // 30*TILE
#define OFF_S  (43 * TILE)  // 4*TILE (CHO, ins, Qsto, food)
#define BUF_F  (47 * TILE)

__device__ __forceinline__ uint32_t smem_u32(const void* p) {
    return (uint32_t)__cvta_generic_to_shared(p);
}

__device__ __forceinline__ uint64_t evict_first_policy() {
    uint64_t pol;
    asm volatile("createpolicy.fractional.L2::evict_first.b64 %0, 1.0;"
                 : "=l"(pol));
    return pol;
}

__device__ __forceinline__ void bulk_ld(uint32_t dst, const void* src,
                                        uint32_t bytes, uint32_t mbar,
                                        uint64_t pol) {
    asm volatile("cp.async.bulk.shared::cta.global.mbarrier::complete_tx::bytes"
                 ".L2::cache_hint [%0], [%1], %2, [%3], %4;"
                 :: "r"(dst), "l"(src), "r"(bytes), "r"(mbar), "l"(pol)
                 : "memory");
}

__global__ void __launch_bounds__(TPB) t1d_dxdt_kernel(
    const float* __restrict__ gx,     // (B,13)
    const float* __restrict__ gp,     // (B,30)
    const float* __restrict__ gCHO,   // (B,)
    const float* __restrict__ gIns,   // (B,)
    const float* __restrict__ gQsto,  // (B,)
    const float* __restrict__ gFood,  // (B,)
    float* __restrict__ gout,         // (B,13)
    int B)
{
    __shared__ __align__(16) float s[BUF_F];
    __shared__ __align__(8)  uint64_t mbar;

    const int tid = threadIdx.x;
    const int rowBase = blockIdx.x * TILE;
    const int nr = min(TILE, B - rowBase);
    const bool bulk_ok = ((nr & 3) == 0);
    const bool active  = (tid < nr);

    const float* gxb = gx + (size_t)rowBase * 13;
    const float* gpb = gp + (size_t)rowBase * 30;
    float* goutb     = gout + (size_t)rowBase * 13;

    const uint32_t mb = smem_u32(&mbar);

    if (bulk_ok) {
        if (tid == 0) {
            asm volatile("mbarrier.init.shared.b64 [%0], %1;" :: "r"(mb), "r"(1u));
        }
        __syncthreads();
        if (tid == 0) {
            const uint64_t pol = evict_first_policy();
            const uint32_t bx = (uint32_t)nr * 13u * 4u;
            const uint32_t bp = (uint32_t)nr * 30u * 4u;
            const uint32_t bs = (uint32_t)nr * 4u;
            asm volatile("mbarrier.arrive.expect_tx.shared.b64 _, [%0], %1;"
                         :: "r"(mb), "r"(bx + bp + 4u * bs) : "memory");
            bulk_ld(smem_u32(s + OFF_X), gxb, bx, mb, pol);
            bulk_ld(smem_u32(s + OFF_P), gpb, bp, mb, pol);
            bulk_ld(smem_u32(s + OFF_S + 0 * TILE), gCHO  + rowBase, bs, mb, pol);
            bulk_ld(smem_u32(s + OFF_S + 1 * TILE), gIns  + rowBase, bs, mb, pol);
            bulk_ld(smem_u32(s + OFF_S + 2 * TILE), gQsto + rowBase, bs, mb, pol);
            bulk_ld(smem_u32(s + OFF_S + 3 * TILE), gFood + rowBase, bs, mb, pol);
        }
        uint32_t done;
        do {
            asm volatile("{\n\t.reg .pred p;\n\t"
                         "mbarrier.try_wait.parity.shared.b64 p, [%1], %2;\n\t"
                         "selp.b32 %0, 1, 0, p;\n\t}"
                         : "=r"(done) : "r"(mb), "r"(0u) : "memory");
        } while (!done);
    } else {
        // tail-safety fallback: scalar staged copies
        for (int j = tid; j < nr * 13; j += TPB) s[OFF_X + j] = gxb[j];
        for (int j = tid; j < nr * 30; j += TPB) s[OFF_P + j] = gpb[j];
        if (active) {
            s[OFF_S + 0 * TILE + tid] = gCHO [rowBase + tid];
            s[OFF_S + 1 * TILE + tid] = gIns [rowBase + tid];
            s[OFF_S + 2 * TILE + tid] = gQsto[rowBase + tid];
            s[OFF_S + 3 * TILE + tid] = gFood[rowBase + tid];
        }
        __syncthreads();
    }

    if (active) {
        const float* X = s + OFF_X + tid * 13;   // stride 13: conflict-free
        const float* P = s + OFF_P + tid * 30;   // stride 30: 2-way, cheap

        float xv[13];
#pragma unroll
        for (int i = 0; i < 13; i++) xv[i] = X[i];

        const float CHO   = s[OFF_S + 0 * TILE + tid];
        const float ins_u = s[OFF_S + 1 * TILE + tid];
        const float lQ    = s[OFF_S + 2 * TILE + tid];
        const float lF    = s[OFF_S + 3 * TILE + tid];

        const float BW      = P[6];
        const float dmg     = CHO * 1000.0f;
        const float insulin = __fdividef(ins_u * 6000.0f, BW);

        const float kmax = P[0], kmin = P[1], b = P[2], d_ = P[3];

        const float qsto = xv[0] + xv[1];
        const float Dbar = lQ + lF;
        const bool  has_food  = (Dbar > 0.0f);
        const float Dbar_safe = has_food ? Dbar : 1.0f;
        const float aa = __fdividef(2.5f, (1.0f - b) * Dbar_safe);
        const float cc = __fdividef(2.5f, d_ * Dbar_safe);
        const float kgut_eating = kmin + (kmax - kmin) * 0.5f *
            (tanhf(aa * (qsto - b * Dbar)) - tanhf(cc * (qsto - d_ * Dbar)) + 2.0f);
        const float kgut = has_food ? kgut_eating : kmax;

        float d[13];
        const float kabs = P[4];
        d[0] = -kmax * xv[0] + dmg;
        d[1] =  kmax * xv[0] - xv[1] * kgut;
        d[2] =  kgut * xv[1] - kabs * xv[2];

        const float Rat  = __fdividef(P[5] * kabs * xv[2], BW);
        const float EGPt = P[7] - P[8] * xv[3] - P[9] * xv[8];
        const float ke1 = P[11], ke2 = P[12];
        const float Et  = (xv[3] > ke2) ? ke1 * (xv[3] - ke2) : 0.0f;
        const float k1 = P[13], k2 = P[14];
        d[3] = (fmaxf(EGPt, 0.0f) + Rat - P[10] - Et - k1 * xv[3] + k2 * xv[4])
               * (xv[3] >= 0.0f ? 1.0f : 0.0f);

        const float Vmt  = P[15] + P[16] * xv[6];
        const float Uidt = __fdividef(Vmt * xv[4], P[17] + xv[4]);
        d[4] = (-Uidt + k1 * xv[3] - k2 * xv[4]) * (xv[4] >= 0.0f ? 1.0f : 0.0f);

        const float m1 = P[18], m2 = P[19];
        const float ka1 = P[22], ka2 = P[23];
        d[5] = (-(m2 + P[20]) * xv[5] + m1 * xv[9] + ka1 * xv[10] + ka2 * xv[11])
               * (xv[5] >= 0.0f ? 1.0f : 0.0f);

        const float It  = __fdividef(xv[5], P[25]);
        const float p2u = P[26];
        const float ki  = P[28];
        d[6]  = -p2u * xv[6] + p2u * (It - P[27]);
        d[7]  = -ki * (xv[7] - It);
        d[8]  = -ki * (xv[8] - xv[7]);
        d[9]  = (-(m1 + P[21]) * xv[9] + m2 * xv[5]) * (xv[9]  >= 0.0f ? 1.0f : 0.0f);
        const float kd = P[24];
        d[10] = (insulin - (ka1 + kd) * xv[10])      * (xv[10] >= 0.0f ? 1.0f : 0.0f);
        d[11] = (kd * xv[10] - ka2 * xv[11])         * (xv[11] >= 0.0f ? 1.0f : 0.0f);
        const float ksc = P[29];
        d[12] = (-ksc * xv[12] + ksc * xv[3])        * (xv[12] >= 0.0f ? 1.0f : 0.0f);

        // each thread overwrites exactly its own row: no barrier needed
        float* O = s + OFF_X + tid * 13;
#pragma unroll
        for (int i = 0; i < 13; i++) O[i] = d[i];
    }
    __syncthreads();

    if (bulk_ok) {
        asm volatile("fence.proxy.async.shared::cta;" ::: "memory");
        if (tid == 0) {
            const uint64_t pol = evict_first_policy();
            asm volatile("cp.async.bulk.global.shared::cta.bulk_group"
                         ".L2::cache_hint [%0], [%1], %2, %3;"
                         :: "l"(goutb), "r"(smem_u32(s + OFF_X)),
                            "r"((uint32_t)nr * 13u * 4u), "l"(pol)
                         : "memory");
            asm volatile("cp.async.bulk.commit_group;" ::: "memory");
            asm volatile("cp.async.bulk.wait_group 0;" ::: "memory");
        }
    } else {
        for (int j = tid; j < nr * 13; j += TPB) goutb[j] = s[OFF_X + j];
    }
}

extern "C" void kernel_launch(void* const* d_in, const int* in_sizes, int n_in,
                              void* d_out, int out_size) {
    const float* gx    = (const float*)d_in[0];  // x (B,13)
    const float* gp    = (const float*)d_in[1];  // params (B,30)
    const float* gCHO  = (const float*)d_in[2];  // CHO (B,)
    const float* gIns  = (const float*)d_in[3];  // insulin (B,)
    const float* gQ    = (const float*)d_in[4];  // last_Qsto (B,)
    const float* gF    = (const float*)d_in[5];  // last_foodtaken (B,)
    float* gout = (float*)d_out;

    const int B = in_sizes[2];  // CHO element count = batch size
    const int grid = (B + TILE - 1) / TILE;
    t1d_dxdt_kernel<<<grid, TPB>>>(gx, gp, gCHO, gIns, gQ, gF, gout, B);
}